// round 15
// baseline (speedup 1.0000x reference)
#include <cuda_runtime.h>
#include <cuda_fp16.h>
#include <cstdint>

// out[b,n] = sum_{c,hw} x[b,c,hw] * W_s[n,hw] * W_d[n,c] + W_b[n]
// GEMM D[(b,c),n] = x . Ws^T via fp16 mma.sync m16n8k16 (fp32 accum).
// A = x stays fp32 (cp.async direct, in-register cvt at fragment time);
// B = Ws pre-converted fp16 (tiny prep). BM=BN=128, 256 thr, 2 CTAs/SM,
// BK=64, 2 stages, quarter-rolling prefetch. Split-K {832,768,768,768}.
// Fused Wd epilogue via atomics (out pre-set to W_b in prep).

#define M_DIM 8192
#define N_DIM 1024
#define K_DIM 3136
#define BM 128
#define BN 128
#define BK 64
#define STAGES 2
#define A_ROW_B 288                    // 64 fp32 (256B) + 32B pad -> banks 8g+2t4
#define B_ROW_B 144                    // 64 fp16 (128B) + 16B pad -> banks 20r
#define A_ST_BYTES (128 * A_ROW_B)     // 36864
#define B_ST_BYTES (128 * B_ROW_B)     // 18432
#define ST_BYTES   (A_ST_BYTES + B_ST_BYTES)   // 55296
#define SMEM_BYTES (STAGES * ST_BYTES)         // 110592 (x2 CTA = 221KB/SM)

__device__ __align__(16) __half g_Bh[(size_t)N_DIM * K_DIM];  // 6.4 MB fp16 Ws

__device__ __forceinline__ void cp_async16(void* s, const void* g) {
    uint32_t sa = (uint32_t)__cvta_generic_to_shared(s);
    asm volatile("cp.async.cg.shared.global [%0], [%1], 16;\n" :: "r"(sa), "l"(g));
}
__device__ __forceinline__ uint32_t pack_h2(float lo, float hi) {
    __half2 h = __floats2half2_rn(lo, hi);
    return *reinterpret_cast<uint32_t*>(&h);
}

// -------- prep: Ws->fp16 (392 blocks, MLP=8) + out=W_b (1 block) --------
__global__ __launch_bounds__(256)
void prep_all(const float* __restrict__ Ws, const float* __restrict__ Wb,
              float* __restrict__ out) {
    const int bid = blockIdx.x;
    const int tid = threadIdx.x;
    if (bid < 392) {                        // Ws: 802,816 float4s, 8/thread
        const size_t base = (size_t)bid * 2048 + tid;
        float4 v[8];
        #pragma unroll
        for (int j = 0; j < 8; j++)
            v[j] = reinterpret_cast<const float4*>(Ws)[base + j * 256];
        #pragma unroll
        for (int j = 0; j < 8; j++) {
            uint2 o;
            o.x = pack_h2(v[j].x, v[j].y);
            o.y = pack_h2(v[j].z, v[j].w);
            reinterpret_cast<uint2*>(g_Bh)[base + j * 256] = o;
        }
    } else {                                // out init: 8192 float4s
        #pragma unroll
        for (int j = 0; j < 32; j++) {
            int oi = tid + j * 256;
            reinterpret_cast<float4*>(out)[oi] =
                reinterpret_cast<const float4*>(Wb)[oi & 255];
        }
    }
}

// ---------------- fused GEMM ----------------
__global__ __launch_bounds__(256, 2)
void gemm_fused(const float* __restrict__ A,
                const float* __restrict__ Wd, float* __restrict__ out) {
    extern __shared__ char smem[];

    const int tid  = threadIdx.x;
    const int warp = tid >> 5;      // 0..7
    const int lane = tid & 31;
    const int wm   = warp & 3;      // 4 warps along M (32 rows)
    const int wn   = warp >> 2;     // 2 warps along N (64 cols)
    const int g    = lane >> 2;
    const int t4   = lane & 3;

    const int gx = blockIdx.x;      // 0..7  N tile
    const int gy = blockIdx.y;      // 0..63 M tile
    const int sp = blockIdx.z;      // 0..3  K split
    const int b  = gy >> 1;
    const int c0 = (gy & 1) * BM;

    const int kst  = (sp == 0) ? 0 : 832 + (sp - 1) * 768;
    const int NT64 = (sp == 0) ? 13 : 12;

    // cp.async: A 2048 chunks (8/thread), B 1024 chunks (4/thread)
    const int ar = tid >> 4, ac = (tid & 15);     // A: rows ar+16i, col ac*16B
    const int br = tid >> 3, bc = (tid & 7);      // B: rows br+32i, col bc*16B
    const float*  apt = A + (size_t)(gy * BM + ar) * K_DIM + kst + ac * 4;
    const __half* bpt = g_Bh + (size_t)(gx * BN + br) * K_DIM + kst + bc * 8;

    // ldmatrix lane map (B)
    const int b_row  = ((lane >> 4) & 1) * 8 + (lane & 7);
    const int b_half = ((lane >> 3) & 1) * 8;

    float acc[2][8][4];
    #pragma unroll
    for (int i = 0; i < 2; i++)
        #pragma unroll
        for (int j = 0; j < 8; j++)
            #pragma unroll
            for (int k = 0; k < 4; k++) acc[i][j][k] = 0.f;

    auto load_stage = [&](int s, int kt) {
        char* st = smem + s * ST_BYTES;
        #pragma unroll
        for (int i = 0; i < 8; i++)
            cp_async16(st + (ar + 16 * i) * A_ROW_B + ac * 16,
                       apt + (size_t)16 * i * K_DIM + kt * 64);
        #pragma unroll
        for (int i = 0; i < 4; i++)
            cp_async16(st + A_ST_BYTES + (br + 32 * i) * B_ROW_B + bc * 16,
                       bpt + (size_t)32 * i * K_DIM + kt * 64);
    };

    load_stage(0, 0);
    asm volatile("cp.async.commit_group;\n" ::: "memory");

    const int abase = (wm * 32 + g) * A_ROW_B + t4 * 8;

    #pragma unroll 1
    for (int kt = 0; kt < NT64; ++kt) {
        asm volatile("cp.async.wait_group 0;\n" ::: "memory");
        __syncthreads();

        if (kt + 1 < NT64) load_stage((kt + 1) & 1, kt + 1);
        asm volatile("cp.async.commit_group;\n" ::: "memory");

        const char* stc = smem + (kt & 1) * ST_BYTES;
        const char* Asb = stc + abase;
        const uint32_t smB = (uint32_t)__cvta_generic_to_shared(stc + A_ST_BYTES);

        uint32_t af[2][2][4], bf[2][8][2];

        // preload quarter 0
        #pragma unroll
        for (int np = 0; np < 4; np++) {
            uint32_t addr = smB + (wn * 64 + np * 16 + b_row) * B_ROW_B + b_half * 2;
            asm volatile(
                "ldmatrix.sync.aligned.m8n8.x4.shared.b16 {%0,%1,%2,%3}, [%4];\n"
                : "=r"(bf[0][2 * np][0]), "=r"(bf[0][2 * np][1]),
                  "=r"(bf[0][2 * np + 1][0]), "=r"(bf[0][2 * np + 1][1])
                : "r"(addr));
        }
        #pragma unroll
        for (int mi = 0; mi < 2; mi++) {
            const char* p = Asb + mi * 16 * A_ROW_B;
            float2 v0 = *(const float2*)(p);
            float2 v1 = *(const float2*)(p + 8 * A_ROW_B);
            float2 v2 = *(const float2*)(p + 32);
            float2 v3 = *(const float2*)(p + 8 * A_ROW_B + 32);
            af[0][mi][0] = pack_h2(v0.x, v0.y);
            af[0][mi][1] = pack_h2(v1.x, v1.y);
            af[0][mi][2] = pack_h2(v2.x, v2.y);
            af[0][mi][3] = pack_h2(v3.x, v3.y);
        }

        #pragma unroll
        for (int q = 0; q < 4; q++) {
            const int cb = q & 1, nb = cb ^ 1;
            // prefetch next-quarter B before this quarter's MMAs
            if (q < 3) {
                #pragma unroll
                for (int np = 0; np < 4; np++) {
                    uint32_t addr = smB + (wn * 64 + np * 16 + b_row) * B_ROW_B
                                  + (q + 1) * 32 + b_half * 2;
                    asm volatile(
                        "ldmatrix.sync.aligned.m8n8.x4.shared.b16 {%0,%1,%2,%3}, [%4];\n"
                        : "=r"(bf[nb][2 * np][0]), "=r"(bf[nb][2 * np][1]),
                          "=r"(bf[nb][2 * np + 1][0]), "=r"(bf[nb][2 * np + 1][1])
                        : "r"(addr));
                }
            }
            // MMAs mi=0
            #pragma unroll
            for (int ni = 0; ni < 8; ni++) {
                asm volatile(
                    "mma.sync.aligned.m16n8k16.row.col.f32.f16.f16.f32 "
                    "{%0,%1,%2,%3}, {%4,%5,%6,%7}, {%8,%9}, {%0,%1,%2,%3};\n"
                    : "+f"(acc[0][ni][0]), "+f"(acc[0][ni][1]),
                      "+f"(acc[0][ni][2]), "+f"(acc[0][ni][3])
                    : "r"(af[cb][0][0]), "r"(af[cb][0][1]),
                      "r"(af[cb][0][2]), "r"(af[cb][0][3]),
                      "r"(bf[cb][ni][0]), "r"(bf[cb][ni][1]));
            }
            // load+convert next-quarter A between the mi halves
            if (q < 3) {
                #pragma unroll
                for (int mi = 0; mi < 2; mi++) {
                    const char* p = Asb + mi * 16 * A_ROW_B + (q + 1) * 64;
                    float2 v0 = *(const float2*)(p);
                    float2 v1 = *(const float2*)(p + 8 * A_ROW_B);
                    float2 v2 = *(const float2*)(p + 32);
                    float2 v3 = *(const float2*)(p + 8 * A_ROW_B + 32);
                    af[nb][mi][0] = pack_h2(v0.x, v0.y);
                    af[nb][mi][1] = pack_h2(v1.x, v1.y);
                    af[nb][mi][2] = pack_h2(v2.x, v2.y);
                    af[nb][mi][3] = pack_h2(v3.x, v3.y);
                }
            }
            // MMAs mi=1
            #pragma unroll
            for (int ni = 0; ni < 8; ni++) {
                asm volatile(
                    "mma.sync.aligned.m16n8k16.row.col.f32.f16.f16.f32 "
                    "{%0,%1,%2,%3}, {%4,%5,%6,%7}, {%8,%9}, {%0,%1,%2,%3};\n"
                    : "+f"(acc[1][ni][0]), "+f"(acc[1][ni][1]),
                      "+f"(acc[1][ni][2]), "+f"(acc[1][ni][3])
                    : "r"(af[cb][1][0]), "r"(af[cb][1][1]),
                      "r"(af[cb][1][2]), "r"(af[cb][1][3]),
                      "r"(bf[cb][ni][0]), "r"(bf[cb][ni][1]));
            }
        }
    }

    // ---------------- fused epilogue ----------------
    // rows: c0 + wm*32 + mi*16 + g (+8); cols: gx*BN + wn*64 + ni*8 + 2*t4 + p
    #pragma unroll
    for (int ni = 0; ni < 8; ni++) {
        #pragma unroll
        for (int p = 0; p < 2; p++) {
            const int n = gx * BN + wn * 64 + ni * 8 + t4 * 2 + p;
            const float* wdp = Wd + (size_t)n * 256 + c0 + wm * 32 + g;
            float s = 0.f;
            #pragma unroll
            for (int mi = 0; mi < 2; mi++) {
                s += acc[mi][ni][p]     * __ldg(wdp + mi * 16);
                s += acc[mi][ni][2 + p] * __ldg(wdp + mi * 16 + 8);
            }
            s += __shfl_xor_sync(0xffffffffu, s, 16);
            s += __shfl_xor_sync(0xffffffffu, s, 8);
            s += __shfl_xor_sync(0xffffffffu, s, 4);
            if (g == 0)
                atomicAdd(&out[(size_t)b * N_DIM + n], s);
        }
    }
}

extern "C" void kernel_launch(void* const* d_in, const int* in_sizes, int n_in,
                              void* d_out, int out_size) {
    const float* x  = (const float*)d_in[0];  // [8192 x 3136]
    const float* Ws = (const float*)d_in[1];  // [1024 x 3136]
    const float* Wd = (const float*)d_in[2];  // [1024 x 256]
    const float* Wb = (const float*)d_in[3];  // [1024]
    float* out = (float*)d_out;               // [32 x 1024] fp32

    static bool attr_set = false;
    if (!attr_set) {
        cudaFuncSetAttribute(gemm_fused,
                             cudaFuncAttributeMaxDynamicSharedMemorySize, SMEM_BYTES);
        attr_set = true;
    }

    prep_all<<<393, 256>>>(Ws, Wb, out);      // Ws -> fp16; out = W_b
    dim3 grid(8, 64, 4);                      // 2048 CTAs
    gemm_fused<<<grid, 256, SMEM_BYTES>>>(x, Wd, out);
}

// round 16
// speedup vs baseline: 1.0581x; 1.0581x over previous
#include <cuda_runtime.h>
#include <cuda_fp16.h>
#include <cstdint>

// out[b,n] = sum_{c,hw} x[b,c,hw] * W_s[n,hw] * W_d[n,c] + W_b[n]
// GEMM D[(b,c),n] = x . Ws^T via fp16 mma.sync m16n8k16 (fp32 accum).
// Both operands pre-converted fp16 (streaming prep, MLP=8); all fragments via
// ldmatrix. BM=BN=128, 256 thr, 2 CTAs/SM, BK=64 (3 stages). Fine-grained
// ldmatrix/MMA interleave (single-x4 prefetch slices between 4-MMA groups).
// Split-K {832,768,768,768}. Fused Wd epilogue + atomics (out pre-set to W_b).

#define M_DIM 8192
#define N_DIM 1024
#define K_DIM 3136
#define BM 128
#define BN 128
#define BK 64
#define STAGES 3
#define ROW_B 144                      // 64 halfs (128B) + 16B pad -> conflict-free
#define A_ST_BYTES (128 * ROW_B)       // 18432
#define ST_BYTES   (2 * A_ST_BYTES)    // 36864
#define SMEM_BYTES (STAGES * ST_BYTES) // 110592 (x2 CTA = 216KB/SM)

__device__ __align__(16) __half g_Ah[(size_t)M_DIM * K_DIM];  // 51.4 MB fp16 x
__device__ __align__(16) __half g_Bh[(size_t)N_DIM * K_DIM];  // 6.4 MB fp16 Ws

__device__ __forceinline__ void cp_async16(void* s, const void* g) {
    uint32_t sa = (uint32_t)__cvta_generic_to_shared(s);
    asm volatile("cp.async.cg.shared.global [%0], [%1], 16;\n" :: "r"(sa), "l"(g));
}
__device__ __forceinline__ uint32_t pack_h2(float lo, float hi) {
    __half2 h = __floats2half2_rn(lo, hi);
    return *reinterpret_cast<uint32_t*>(&h);
}

// -------- prep: x->fp16 (3136 blocks), Ws->fp16 (392), out=W_b (1) --------
__global__ __launch_bounds__(256)
void prep_all(const float* __restrict__ x, const float* __restrict__ Ws,
              const float* __restrict__ Wb, float* __restrict__ out) {
    const int bid = blockIdx.x;
    const int tid = threadIdx.x;
    if (bid < 3136) {                       // x: 6,422,528 float4s, 8/thread
        const size_t base = (size_t)bid * 2048 + tid;
        float4 v[8];
        #pragma unroll
        for (int j = 0; j < 8; j++)
            v[j] = reinterpret_cast<const float4*>(x)[base + j * 256];
        #pragma unroll
        for (int j = 0; j < 8; j++) {
            uint2 o;
            o.x = pack_h2(v[j].x, v[j].y);
            o.y = pack_h2(v[j].z, v[j].w);
            reinterpret_cast<uint2*>(g_Ah)[base + j * 256] = o;
        }
    } else if (bid < 3528) {                // Ws: 802,816 float4s, 8/thread
        const size_t base = (size_t)(bid - 3136) * 2048 + tid;
        float4 v[8];
        #pragma unroll
        for (int j = 0; j < 8; j++)
            v[j] = reinterpret_cast<const float4*>(Ws)[base + j * 256];
        #pragma unroll
        for (int j = 0; j < 8; j++) {
            uint2 o;
            o.x = pack_h2(v[j].x, v[j].y);
            o.y = pack_h2(v[j].z, v[j].w);
            reinterpret_cast<uint2*>(g_Bh)[base + j * 256] = o;
        }
    } else {                                // out init: 8192 float4s
        #pragma unroll
        for (int j = 0; j < 32; j++) {
            int oi = tid + j * 256;
            reinterpret_cast<float4*>(out)[oi] =
                reinterpret_cast<const float4*>(Wb)[oi & 255];
        }
    }
}

// ldmatrix.x4 + mma helpers (macros so the interleave stays explicit)
#define LDSM4(r0, r1, r2, r3, addr)                                          \
    asm volatile("ldmatrix.sync.aligned.m8n8.x4.shared.b16 {%0,%1,%2,%3}, [%4];\n" \
                 : "=r"(r0), "=r"(r1), "=r"(r2), "=r"(r3) : "r"(addr))

#define MMA16816(d, a, bv)                                                   \
    asm volatile("mma.sync.aligned.m16n8k16.row.col.f32.f16.f16.f32 "        \
                 "{%0,%1,%2,%3}, {%4,%5,%6,%7}, {%8,%9}, {%0,%1,%2,%3};\n"   \
                 : "+f"((d)[0]), "+f"((d)[1]), "+f"((d)[2]), "+f"((d)[3])    \
                 : "r"((a)[0]), "r"((a)[1]), "r"((a)[2]), "r"((a)[3]),       \
                   "r"((bv)[0]), "r"((bv)[1]))

// ---------------- fused GEMM ----------------
__global__ __launch_bounds__(256, 2)
void gemm_fused(const float* __restrict__ Wd, float* __restrict__ out) {
    extern __shared__ char smem[];

    const int tid  = threadIdx.x;
    const int warp = tid >> 5;      // 0..7
    const int lane = tid & 31;
    const int wm   = warp & 3;      // 4 warps along M (32 rows)
    const int wn   = warp >> 2;     // 2 warps along N (64 cols)
    const int g    = lane >> 2;
    const int t4   = lane & 3;

    const int gx = blockIdx.x;      // 0..7  N tile
    const int gy = blockIdx.y;      // 0..63 M tile
    const int sp = blockIdx.z;      // 0..3  K split
    const int b  = gy >> 1;
    const int c0 = (gy & 1) * BM;

    const int kst  = (sp == 0) ? 0 : 832 + (sp - 1) * 768;
    const int NT64 = (sp == 0) ? 13 : 12;

    // cp.async: 1024 chunks each for A and B; 4/thread each
    const int crow = tid >> 3;                 // 0..31 (+32*i)
    const int ccol = (tid & 7) * 16;           // byte offset in row
    const __half* apt = g_Ah + (size_t)(gy * BM + crow) * K_DIM + kst + (ccol >> 1);
    const __half* bpt = g_Bh + (size_t)(gx * BN + crow) * K_DIM + kst + (ccol >> 1);

    // ldmatrix lane maps
    const int a_row  = (lane & 7) + ((lane >> 3) & 1) * 8;
    const int a_ko   = (lane >> 4) & 1;
    const int b_row  = ((lane >> 4) & 1) * 8 + (lane & 7);
    const int b_half = ((lane >> 3) & 1) * 8;

    float acc[2][8][4];
    #pragma unroll
    for (int i = 0; i < 2; i++)
        #pragma unroll
        for (int j = 0; j < 8; j++)
            #pragma unroll
            for (int k = 0; k < 4; k++) acc[i][j][k] = 0.f;

    auto load_stage = [&](int s, int kt) {
        char* st = smem + s * ST_BYTES;
        #pragma unroll
        for (int i = 0; i < 4; i++)
            cp_async16(st + (crow + 32 * i) * ROW_B + ccol,
                       apt + (size_t)32 * i * K_DIM + kt * 64);
        #pragma unroll
        for (int i = 0; i < 4; i++)
            cp_async16(st + A_ST_BYTES + (crow + 32 * i) * ROW_B + ccol,
                       bpt + (size_t)32 * i * K_DIM + kt * 64);
    };

    load_stage(0, 0);
    asm volatile("cp.async.commit_group;\n" ::: "memory");
    load_stage(1, 1);
    asm volatile("cp.async.commit_group;\n" ::: "memory");

    int s_cur = 0, s_load = 2;
    #pragma unroll 1
    for (int kt = 0; kt < NT64; ++kt) {
        asm volatile("cp.async.wait_group 1;\n" ::: "memory");
        __syncthreads();

        if (kt + 2 < NT64) load_stage(s_load, kt + 2);
        asm volatile("cp.async.commit_group;\n" ::: "memory");

        const uint32_t smA = (uint32_t)__cvta_generic_to_shared(smem + s_cur * ST_BYTES);
        const uint32_t smB = smA + A_ST_BYTES;
        // per-warp ldmatrix base addresses
        const uint32_t aAd0 = smA + (wm * 32 + a_row) * ROW_B + a_ko * 16;
        const uint32_t aAd1 = smA + (wm * 32 + 16 + a_row) * ROW_B + a_ko * 16;
        const uint32_t bBd  = smB + (wn * 64 + b_row) * ROW_B + b_half * 2;

        uint32_t af[2][2][4], bf[2][8][2];

        // preload quarter 0
        #pragma unroll
        for (int np = 0; np < 4; np++)
            LDSM4(bf[0][2 * np][0], bf[0][2 * np][1],
                  bf[0][2 * np + 1][0], bf[0][2 * np + 1][1],
                  bBd + np * 16 * ROW_B);
        LDSM4(af[0][0][0], af[0][0][1], af[0][0][2], af[0][0][3], aAd0);
        LDSM4(af[0][1][0], af[0][1][1], af[0][1][2], af[0][1][3], aAd1);

        #pragma unroll
        for (int q = 0; q < 4; q++) {
            const int cb = q & 1, nb = cb ^ 1;
            const int qo = (q + 1) * 32;           // next-quarter byte offset
            // finely interleaved: one ldmatrix slice per 4-MMA group
            if (q < 3)
                LDSM4(bf[nb][0][0], bf[nb][0][1], bf[nb][1][0], bf[nb][1][1],
                      bBd + qo);
            MMA16816(acc[0][0], af[cb][0], bf[cb][0]);
            MMA16816(acc[0][1], af[cb][0], bf[cb][1]);
            MMA16816(acc[0][2], af[cb][0], bf[cb][2]);
            MMA16816(acc[0][3], af[cb][0], bf[cb][3]);
            if (q < 3)
                LDSM4(bf[nb][2][0], bf[nb][2][1], bf[nb][3][0], bf[nb][3][1],
                      bBd + 16 * ROW_B + qo);
            MMA16816(acc[0][4], af[cb][0], bf[cb][4]);
            MMA16816(acc[0][5], af[cb][0], bf[cb][5]);
            MMA16816(acc[0][6], af[cb][0], bf[cb][6]);
            MMA16816(acc[0][7], af[cb][0], bf[cb][7]);
            if (q < 3)
                LDSM4(bf[nb][4][0], bf[nb][4][1], bf[nb][5][0], bf[nb][5][1],
                      bBd + 32 * ROW_B + qo);
            MMA16816(acc[1][0], af[cb][1], bf[cb][0]);
            MMA16816(acc[1][1], af[cb][1], bf[cb][1]);
            MMA16816(acc[1][2], af[cb][1], bf[cb][2]);
            MMA16816(acc[1][3], af[cb][1], bf[cb][3]);
            if (q < 3) {
                LDSM4(bf[nb][6][0], bf[nb][6][1], bf[nb][7][0], bf[nb][7][1],
                      bBd + 48 * ROW_B + qo);
                LDSM4(af[nb][0][0], af[nb][0][1], af[nb][0][2], af[nb][0][3],
                      aAd0 + qo);
                LDSM4(af[nb][1][0], af[nb][1][1], af[nb][1][2], af[nb][1][3],
                      aAd1 + qo);
            }
            MMA16816(acc[1][4], af[cb][1], bf[cb][4]);
            MMA16816(acc[1][5], af[cb][1], bf[cb][5]);
            MMA16816(acc[1][6], af[cb][1], bf[cb][6]);
            MMA16816(acc[1][7], af[cb][1], bf[cb][7]);
        }

        s_cur  = (s_cur  == STAGES - 1) ? 0 : s_cur + 1;
        s_load = (s_load == STAGES - 1) ? 0 : s_load + 1;
    }

    // ---------------- fused epilogue ----------------
    // rows: c0 + wm*32 + mi*16 + g (+8); cols: gx*BN + wn*64 + ni*8 + 2*t4 + p
    #pragma unroll
    for (int ni = 0; ni < 8; ni++) {
        #pragma unroll
        for (int p = 0; p < 2; p++) {
            const int n = gx * BN + wn * 64 + ni * 8 + t4 * 2 + p;
            const float* wdp = Wd + (size_t)n * 256 + c0 + wm * 32 + g;
            float s = 0.f;
            #pragma unroll
            for (int mi = 0; mi < 2; mi++) {
                s += acc[mi][ni][p]     * __ldg(wdp + mi * 16);
                s += acc[mi][ni][2 + p] * __ldg(wdp + mi * 16 + 8);
            }
            s += __shfl_xor_sync(0xffffffffu, s, 16);
            s += __shfl_xor_sync(0xffffffffu, s, 8);
            s += __shfl_xor_sync(0xffffffffu, s, 4);
            if (g == 0)
                atomicAdd(&out[(size_t)b * N_DIM + n], s);
        }
    }
}

extern "C" void kernel_launch(void* const* d_in, const int* in_sizes, int n_in,
                              void* d_out, int out_size) {
    const float* x  = (const float*)d_in[0];  // [8192 x 3136]
    const float* Ws = (const float*)d_in[1];  // [1024 x 3136]
    const float* Wd = (const float*)d_in[2];  // [1024 x 256]
    const float* Wb = (const float*)d_in[3];  // [1024]
    float* out = (float*)d_out;               // [32 x 1024] fp32

    static bool attr_set = false;
    if (!attr_set) {
        cudaFuncSetAttribute(gemm_fused,
                             cudaFuncAttributeMaxDynamicSharedMemorySize, SMEM_BYTES);
        attr_set = true;
    }

    prep_all<<<3529, 256>>>(x, Ws, Wb, out);  // x,Ws -> fp16 (MLP=8); out = W_b
    dim3 grid(8, 64, 4);                      // 2048 CTAs
    gemm_fused<<<grid, 256, SMEM_BYTES>>>(Wd, out);
}